// round 10
// baseline (speedup 1.0000x reference)
#include <cuda_runtime.h>
#include <cuda_fp16.h>
#include <cstdint>

#define B_   8
#define T_   16
#define H_   64
#define W_   64
#define CIN  32
#define F_   64
#define NC   256          // 4*F gates [i,f,c,o]
#define NSL  27           // 9 x-slices + 18 h-slices (K=32 each)
#define NHS  18           // h-slices in step kernel

// Persistent state. h in fp16 (feeds fp16 MMA), c in fp32.
__device__ __half g_hh[2][B_ * H_ * W_ * F_];
__device__ float  g_c[B_ * H_ * W_ * F_];
// x pre-converted to fp16
__device__ __half g_xh[B_ * T_ * H_ * W_ * CIN];
// Weights pre-packed in MMA B-fragment order (verified R5/R7):
// [slice][warp_n][idx = kk*4+p][lane] -> uint4
__device__ uint4 g_bf[NSL][4][8][32];
// Precomputed x-conv pre-activations, stored in per-thread D-fragment order:
// [t][b][tile][warp][chunk][lane], chunk = mt*4 + ntpair
__device__ uint4 g_zx[T_][B_][64][8][8][32];   // 268.4 MB fp16

#define HH_PITCH 144    // bytes per halo pixel row (h: 128B data + pad)
#define XH_PITCH 80     // bytes per halo pixel row (x: 64B data + pad)

__device__ __forceinline__ float hsig(float x) {
    return __saturatef((x + 3.0f) * 0.16666667f);  // hard_sigmoid
}
__device__ __forceinline__ uint32_t smem_u32(const void* p) {
    uint32_t a;
    asm("{ .reg .u64 t; cvta.to.shared.u64 t, %1; cvt.u32.u64 %0, t; }"
        : "=r"(a) : "l"(p));
    return a;
}

#define LDSM4(r0, r1, r2, r3, addr) \
    asm volatile("ldmatrix.sync.aligned.m8n8.x4.shared.b16 {%0,%1,%2,%3}, [%4];" \
        : "=r"(r0), "=r"(r1), "=r"(r2), "=r"(r3) : "r"(addr))

#define MMA16816(d, a0, a1, a2, a3, b0, b1) \
    asm volatile("mma.sync.aligned.m16n8k16.row.col.f32.f16.f16.f32 " \
        "{%0,%1,%2,%3}, {%4,%5,%6,%7}, {%8,%9}, {%0,%1,%2,%3};" \
        : "+f"((d)[0]), "+f"((d)[1]), "+f"((d)[2]), "+f"((d)[3]) \
        : "r"(a0), "r"(a1), "r"(a2), "r"(a3), "r"(b0), "r"(b1))

// ---- one-time preps ----
__global__ void prep_x(const float* __restrict__ x) {
    size_t i = ((size_t)blockIdx.x * 256 + threadIdx.x) * 4;
    float4 v = *(const float4*)(x + i);
    __half2 h2[2];
    h2[0] = __floats2half2_rn(v.x, v.y);
    h2[1] = __floats2half2_rn(v.z, v.w);
    *(uint2*)&g_xh[i] = *(uint2*)h2;
}

// Pack weights into B-fragment order (verified R5/R7).
__global__ void prep_bf(const float* __restrict__ Wt,
                        const float* __restrict__ Ut) {
    const int s    = blockIdx.x;          // 0..26
    const int wn   = blockIdx.y;          // 0..3
    const int idx  = threadIdx.x >> 5;    // 0..7
    const int lane = threadIdx.x & 31;
    const int kk = idx >> 2, p = idx & 3;

    uint32_t r[4];
    #pragma unroll
    for (int jm = 0; jm < 4; ++jm) {
        const int a  = 8 * jm + (lane >> 2);
        const int n  = wn * 64 + p * 16 + ((a >> 4) << 3) + (a & 7);
        const int jcol = ((n >> 4) & 3) * 64 + (n >> 6) * 16 + (n & 15);
        const int kb = kk * 16 + ((a >> 3) & 1) * 8 + 2 * (lane & 3);
        float w0, w1;
        if (s < 9) {
            const float* bp = Wt + ((size_t)s * CIN + kb) * NC + jcol;
            w0 = bp[0]; w1 = bp[NC];
        } else {
            const int u = s - 9, k9 = u >> 1, c0 = (u & 1) * 32;
            const float* bp = Ut + ((size_t)k9 * F_ + c0 + kb) * NC + jcol;
            w0 = bp[0]; w1 = bp[NC];
        }
        __half2 h2 = __floats2half2_rn(w0, w1);
        r[jm] = *(uint32_t*)&h2;
    }
    g_bf[s][wn][idx][lane] = make_uint4(r[0], r[1], r[2], r[3]);
}

#define SLICE_BODY(A0, A1, SOFF, NSX)                                         \
do {                                                                          \
    const uint4* bnp = bp + ((s + 1 < (NSX)) ? (4 * 8 * 32) : 0);             \
    _Pragma("unroll")                                                         \
    for (int kk = 0; kk < 2; ++kk) {                                          \
        uint32_t a0r[4], a1r[4];                                              \
        LDSM4(a0r[0], a0r[1], a0r[2], a0r[3], (A0) + (SOFF) + kk * 32);       \
        LDSM4(a1r[0], a1r[1], a1r[2], a1r[3], (A1) + (SOFF) + kk * 32);       \
        _Pragma("unroll")                                                     \
        for (int p = 0; p < 4; ++p) {                                         \
            const int idx = kk * 4 + p;                                       \
            const uint4* pf = (idx + 2 < 8) ? (bp + (idx + 2) * 32)           \
                                            : (bnp + (idx - 6) * 32);         \
            uint4 nb = *pf;                                                   \
            uint4 cb = bb[p];                                                 \
            MMA16816(d[0][2 * p + 0], a0r[0], a0r[1], a0r[2], a0r[3], cb.x, cb.y); \
            MMA16816(d[0][2 * p + 1], a0r[0], a0r[1], a0r[2], a0r[3], cb.z, cb.w); \
            MMA16816(d[1][2 * p + 0], a1r[0], a1r[1], a1r[2], a1r[3], cb.x, cb.y); \
            MMA16816(d[1][2 * p + 1], a1r[0], a1r[1], a1r[2], a1r[3], cb.z, cb.w); \
            bb[(p + 2) & 3] = nb;                                             \
        }                                                                     \
    }                                                                         \
    bp = bnp;                                                                 \
} while (0)

// ---- batched x-conv over ALL timesteps (no sequential dependency) ----
// CTA: 8x8 px (M=64) x N=256, 8 warps (2m x 4n). Stores raw fragments.
__global__ __launch_bounds__(256, 2)
void conv_x(int dummy)
{
    __shared__ __align__(16) char sm[100 * XH_PITCH];

    const int tid  = threadIdx.x;
    const int lane = tid & 31;
    const int w    = tid >> 5;
    const int warp_m = w & 1;
    const int warp_n = w >> 1;
    const int bt = blockIdx.z;
    const int b = bt >> 4, t = bt & 15;
    const int y0 = blockIdx.y * 8;
    const int x0 = blockIdx.x * 8;

    const __half* xframe = g_xh + (size_t)(b * T_ + t) * H_ * W_ * CIN;

    for (int j = tid; j < 400; j += 256) {            // x halo: 100 px * 4
        const int p = j >> 2, q = j & 3;
        const int gy = y0 + p / 10 - 1, gx = x0 + p % 10 - 1;
        uint4 v = make_uint4(0u, 0u, 0u, 0u);
        if ((unsigned)gy < H_ && (unsigned)gx < W_)
            v = *(const uint4*)(xframe + ((size_t)gy * W_ + gx) * CIN + q * 8);
        *(uint4*)(sm + p * XH_PITCH + q * 16) = v;
    }
    __syncthreads();

    const uint32_t sb = smem_u32(sm);
    const int hi  = (lane >> 4) << 4;
    const int m0  = warp_m * 32 + (lane & 15);
    const int m1  = m0 + 16;
    const int f0p = (m0 >> 3) * 10 + (m0 & 7);
    const int f1p = (m1 >> 3) * 10 + (m1 & 7);
    const uint32_t aAx0 = sb + f0p * XH_PITCH + hi;
    const uint32_t aAx1 = sb + f1p * XH_PITCH + hi;

    float d[2][8][4];
    #pragma unroll
    for (int mt = 0; mt < 2; ++mt)
        #pragma unroll
        for (int nt = 0; nt < 8; ++nt)
            #pragma unroll
            for (int c = 0; c < 4; ++c) d[mt][nt][c] = 0.f;

    const uint4* bp = &g_bf[0][warp_n][0][lane];
    uint4 bb[4];
    bb[0] = bp[0];
    bb[1] = bp[32];

    for (int s = 0; s < 9; ++s) {
        const int ky = s / 3, kx = s - 3 * (s / 3);
        const uint32_t soff = (uint32_t)(ky * 10 + kx) * XH_PITCH;
        SLICE_BODY(aAx0, aAx1, soff, 9);
    }

    // store fragments as fp16 pairs
    const int tile = blockIdx.y * 8 + blockIdx.x;
    uint4* dst = &g_zx[t][b][tile][w][0][lane];
    #pragma unroll
    for (int mt = 0; mt < 2; ++mt)
        #pragma unroll
        for (int np = 0; np < 4; ++np) {
            uint4 v;
            __half2 h0 = __floats2half2_rn(d[mt][2*np+0][0], d[mt][2*np+0][1]);
            __half2 h1 = __floats2half2_rn(d[mt][2*np+0][2], d[mt][2*np+0][3]);
            __half2 h2 = __floats2half2_rn(d[mt][2*np+1][0], d[mt][2*np+1][1]);
            __half2 h3 = __floats2half2_rn(d[mt][2*np+1][2], d[mt][2*np+1][3]);
            v.x = *(uint32_t*)&h0; v.y = *(uint32_t*)&h1;
            v.z = *(uint32_t*)&h2; v.w = *(uint32_t*)&h3;
            dst[(mt * 4 + np) * 32] = v;
        }
}

// ---- sequential step: h-conv (18 slices) + fused LSTM epilogue ----
template<bool FIRST>
__global__ __launch_bounds__(256, 2)
void step_mma(const float* __restrict__ bias, int t, int hsel,
              float* __restrict__ out, int last)
{
    __shared__ __align__(16) char sm[100 * HH_PITCH];

    const int tid  = threadIdx.x;
    const int lane = tid & 31;
    const int w    = tid >> 5;
    const int warp_m = w & 1;
    const int warp_n = w >> 1;
    const int b  = blockIdx.z;
    const int y0 = blockIdx.y * 8;
    const int x0 = blockIdx.x * 8;
    const int tile = blockIdx.y * 8 + blockIdx.x;

    // init accumulators from precomputed x-conv fragments
    float d[2][8][4];
    {
        const uint4* zsrc = &g_zx[t][b][tile][w][0][lane];
        #pragma unroll
        for (int mt = 0; mt < 2; ++mt)
            #pragma unroll
            for (int np = 0; np < 4; ++np) {
                uint4 v = zsrc[(mt * 4 + np) * 32];
                float2 f0 = __half22float2(*(__half2*)&v.x);
                float2 f1 = __half22float2(*(__half2*)&v.y);
                float2 f2 = __half22float2(*(__half2*)&v.z);
                float2 f3 = __half22float2(*(__half2*)&v.w);
                d[mt][2*np+0][0] = f0.x; d[mt][2*np+0][1] = f0.y;
                d[mt][2*np+0][2] = f1.x; d[mt][2*np+0][3] = f1.y;
                d[mt][2*np+1][0] = f2.x; d[mt][2*np+1][1] = f2.y;
                d[mt][2*np+1][2] = f3.x; d[mt][2*np+1][3] = f3.y;
            }
    }

    if (!FIRST) {
        const __half* hframe = g_hh[hsel] + (size_t)b * H_ * W_ * F_;
        for (int j = tid; j < 800; j += 256) {        // h halo: 100 px * 8
            const int p = j >> 3, q = j & 7;
            const int gy = y0 + p / 10 - 1, gx = x0 + p % 10 - 1;
            uint4 v = make_uint4(0u, 0u, 0u, 0u);
            if ((unsigned)gy < H_ && (unsigned)gx < W_)
                v = *(const uint4*)(hframe + ((size_t)gy * W_ + gx) * F_ + q * 8);
            *(uint4*)(sm + p * HH_PITCH + q * 16) = v;
        }
        __syncthreads();

        const uint32_t sb = smem_u32(sm);
        const int hi  = (lane >> 4) << 4;
        const int m0  = warp_m * 32 + (lane & 15);
        const int m1  = m0 + 16;
        const int f0p = (m0 >> 3) * 10 + (m0 & 7);
        const int f1p = (m1 >> 3) * 10 + (m1 & 7);
        const uint32_t aAh0 = sb + f0p * HH_PITCH + hi;
        const uint32_t aAh1 = sb + f1p * HH_PITCH + hi;

        const uint4* bp = &g_bf[9][warp_n][0][lane];
        uint4 bb[4];
        bb[0] = bp[0];
        bb[1] = bp[32];

        for (int s = 0; s < NHS; ++s) {
            const int k9 = s >> 1, c0 = (s & 1) * 32;
            const int ky = k9 / 3, kx = k9 - 3 * (k9 / 3);
            const uint32_t soff = (uint32_t)(ky * 10 + kx) * HH_PITCH + c0 * 2;
            SLICE_BODY(aAh0, aAh1, soff, NHS);
        }
    }

    // ================= fused LSTM epilogue (verified layout) ==============
    __half* hhout = g_hh[hsel ^ 1];
    const int fq = 2 * (lane & 3);

    #pragma unroll
    for (int mt = 0; mt < 2; ++mt) {
        #pragma unroll
        for (int rh = 0; rh < 2; ++rh) {
            const int m  = warp_m * 32 + mt * 16 + rh * 8 + (lane >> 2);
            const int py = m >> 3, px = m & 7;
            const size_t pix =
                (((size_t)b * H_ + (y0 + py)) * W_ + (x0 + px)) * F_;
            #pragma unroll
            for (int t1 = 0; t1 < 2; ++t1) {
                const int f0 = warp_n * 16 + t1 * 8 + fq;
                float zi0 = d[mt][0 + t1][rh * 2 + 0], zi1 = d[mt][0 + t1][rh * 2 + 1];
                float zf0 = d[mt][2 + t1][rh * 2 + 0], zf1 = d[mt][2 + t1][rh * 2 + 1];
                float zc0 = d[mt][4 + t1][rh * 2 + 0], zc1 = d[mt][4 + t1][rh * 2 + 1];
                float zo0 = d[mt][6 + t1][rh * 2 + 0], zo1 = d[mt][6 + t1][rh * 2 + 1];

                float2 co = make_float2(0.f, 0.f);
                if (!FIRST) co = *(const float2*)&g_c[pix + f0];

                float ig0 = hsig(zi0 + bias[f0]);
                float fg0 = hsig(zf0 + bias[64 + f0]);
                float zz0 =      zc0 + bias[128 + f0];
                float og0 = hsig(zo0 + bias[192 + f0]);
                float cn0 = fg0 * co.x + ig0 * fmaxf(zz0, 0.f);
                float hn0 = og0 * fmaxf(cn0, 0.f);

                float ig1 = hsig(zi1 + bias[f0 + 1]);
                float fg1 = hsig(zf1 + bias[65 + f0]);
                float zz1 =      zc1 + bias[129 + f0];
                float og1 = hsig(zo1 + bias[193 + f0]);
                float cn1 = fg1 * co.y + ig1 * fmaxf(zz1, 0.f);
                float hn1 = og1 * fmaxf(cn1, 0.f);

                if (!last) {
                    *(float2*)&g_c[pix + f0] = make_float2(cn0, cn1);
                    *(__half2*)&hhout[pix + f0] = __floats2half2_rn(hn0, hn1);
                } else {
                    *(float2*)&out[pix + f0] = make_float2(hn0, hn1);
                }
            }
        }
    }
}

extern "C" void kernel_launch(void* const* d_in, const int* in_sizes, int n_in,
                              void* d_out, int out_size)
{
    const float* x = nullptr; const float* Wt = nullptr;
    const float* Ut = nullptr; const float* bias = nullptr;
    for (int i = 0; i < n_in; ++i) {
        switch (in_sizes[i]) {
            case B_*T_*H_*W_*CIN: x    = (const float*)d_in[i]; break;
            case 3*3*CIN*NC:      Wt   = (const float*)d_in[i]; break;
            case 3*3*F_*NC:       Ut   = (const float*)d_in[i]; break;
            case NC:              bias = (const float*)d_in[i]; break;
        }
    }
    if (!x || !Wt || !Ut || !bias) {
        x = (const float*)d_in[0]; Wt = (const float*)d_in[1];
        Ut = (const float*)d_in[2]; bias = (const float*)d_in[3];
    }
    float* out = (float*)d_out;

    prep_x<<<(B_ * T_ * H_ * W_ * CIN) / 1024, 256>>>(x);
    prep_bf<<<dim3(NSL, 4), 256>>>(Wt, Ut);

    dim3 block(256);
    // batched x-conv for all timesteps (fully parallel)
    conv_x<<<dim3(W_ / 8, H_ / 8, B_ * T_), block>>>(0);

    dim3 grid(W_ / 8, H_ / 8, B_);    // 512 CTAs per step
    step_mma<true><<<grid, block>>>(bias, 0, 0, out, 0);
    for (int t = 1; t < T_; ++t) {
        int last = (t == T_ - 1);
        step_mma<false><<<grid, block>>>(bias, t, t & 1, out, last);
    }
}

// round 11
// speedup vs baseline: 1.4666x; 1.4666x over previous
#include <cuda_runtime.h>
#include <cuda_fp16.h>
#include <cstdint>

#define B_   8
#define T_   16
#define H_   64
#define W_   64
#define CIN  32
#define F_   64
#define NC   256          // 4*F gates [i,f,c,o]
#define NSL  27           // 9 x-slices + 18 h-slices (K=32 each)

// Persistent state. h in fp16 (feeds fp16 MMA), c in fp32.
__device__ __half g_hh[2][B_ * H_ * W_ * F_];
__device__ float  g_c[B_ * H_ * W_ * F_];
// x pre-converted to fp16
__device__ __half g_xh[B_ * T_ * H_ * W_ * CIN];
// Weights pre-packed in MMA B-fragment order (verified R5/R7):
// [slice][warp_n][idx = kk*4+p][lane] -> uint4
__device__ uint4 g_bf[NSL][4][8][32];

// Halo tile: 18 rows x 10 cols = 180 pixels (16x8 interior + 1 halo ring)
#define XH_PITCH 80     // bytes per halo pixel row (x: 64B data + pad)
#define HH_PITCH 144    // bytes per halo pixel row (h: 128B data + pad)
#define SM_XH 0
#define SM_HH (180 * XH_PITCH)                 // 14400
#define SM_TOT (SM_HH + 180 * HH_PITCH)        // 40320 B (static)

__device__ __forceinline__ float hsig(float x) {
    return __saturatef((x + 3.0f) * 0.16666667f);  // hard_sigmoid
}
__device__ __forceinline__ uint32_t smem_u32(const void* p) {
    uint32_t a;
    asm("{ .reg .u64 t; cvta.to.shared.u64 t, %1; cvt.u32.u64 %0, t; }"
        : "=r"(a) : "l"(p));
    return a;
}

#define LDSM4(r0, r1, r2, r3, addr) \
    asm volatile("ldmatrix.sync.aligned.m8n8.x4.shared.b16 {%0,%1,%2,%3}, [%4];" \
        : "=r"(r0), "=r"(r1), "=r"(r2), "=r"(r3) : "r"(addr))

#define MMA16816(d, a0, a1, a2, a3, b0, b1) \
    asm volatile("mma.sync.aligned.m16n8k16.row.col.f32.f16.f16.f32 " \
        "{%0,%1,%2,%3}, {%4,%5,%6,%7}, {%8,%9}, {%0,%1,%2,%3};" \
        : "+f"((d)[0]), "+f"((d)[1]), "+f"((d)[2]), "+f"((d)[3]) \
        : "r"(a0), "r"(a1), "r"(a2), "r"(a3), "r"(b0), "r"(b1))

// ---- one-time preps ----
__global__ void prep_x(const float* __restrict__ x) {
    size_t i = ((size_t)blockIdx.x * 256 + threadIdx.x) * 4;
    float4 v = *(const float4*)(x + i);
    __half2 h2[2];
    h2[0] = __floats2half2_rn(v.x, v.y);
    h2[1] = __floats2half2_rn(v.z, v.w);
    *(uint2*)&g_xh[i] = *(uint2*)h2;
}

// Pack weights into B-fragment order (verified R5/R7).
__global__ void prep_bf(const float* __restrict__ Wt,
                        const float* __restrict__ Ut) {
    const int s    = blockIdx.x;          // 0..26
    const int wn   = blockIdx.y;          // 0..3
    const int idx  = threadIdx.x >> 5;    // 0..7
    const int lane = threadIdx.x & 31;
    const int kk = idx >> 2, p = idx & 3;

    uint32_t r[4];
    #pragma unroll
    for (int jm = 0; jm < 4; ++jm) {
        const int a  = 8 * jm + (lane >> 2);
        const int n  = wn * 64 + p * 16 + ((a >> 4) << 3) + (a & 7);
        const int jcol = ((n >> 4) & 3) * 64 + (n >> 6) * 16 + (n & 15);
        const int kb = kk * 16 + ((a >> 3) & 1) * 8 + 2 * (lane & 3);
        float w0, w1;
        if (s < 9) {
            const float* bp = Wt + ((size_t)s * CIN + kb) * NC + jcol;
            w0 = bp[0]; w1 = bp[NC];
        } else {
            const int u = s - 9, k9 = u >> 1, c0 = (u & 1) * 32;
            const float* bp = Ut + ((size_t)k9 * F_ + c0 + kb) * NC + jcol;
            w0 = bp[0]; w1 = bp[NC];
        }
        __half2 h2 = __floats2half2_rn(w0, w1);
        r[jm] = *(uint32_t*)&h2;
    }
    g_bf[s][wn][idx][lane] = make_uint4(r[0], r[1], r[2], r[3]);
}

// One ConvLSTM timestep. CTA: 16x8 pixels (M=128) x N=256, 512 threads,
// 16 warps (4m x 4n); warp tile 32x64 (identical per-warp code to R7).
// 4 m-warps share each B LDG stream -> 3/4 of B requests are L1 hits.
// Persistent halos; zero barriers in mainloop; distance-2 B register ring.
template<bool FIRST>
__global__ __launch_bounds__(512, 1)
void step_mma(const float* __restrict__ bias, int t, int hsel,
              float* __restrict__ out, int last)
{
    __shared__ __align__(16) char sm[SM_TOT];

    const int tid  = threadIdx.x;
    const int lane = tid & 31;
    const int w    = tid >> 5;
    const int warp_m = w & 3;        // 4 m-warps
    const int warp_n = w >> 2;       // 4 n-warps
    const int b  = blockIdx.z;
    const int y0 = blockIdx.y * 16;
    const int x0 = blockIdx.x * 8;

    const __half* xframe = g_xh + (size_t)(b * T_ + t) * H_ * W_ * CIN;
    const __half* hframe = g_hh[hsel] + (size_t)b * H_ * W_ * F_;

    // ---- stage halos once (18 rows x 10 cols) ----
    for (int j = tid; j < 720; j += 512) {            // x: 180 px * 4 chunks
        const int p = j >> 2, q = j & 3;
        const int gy = y0 + p / 10 - 1, gx = x0 + p % 10 - 1;
        uint4 v = make_uint4(0u, 0u, 0u, 0u);
        if ((unsigned)gy < H_ && (unsigned)gx < W_)
            v = *(const uint4*)(xframe + ((size_t)gy * W_ + gx) * CIN + q * 8);
        *(uint4*)(sm + SM_XH + p * XH_PITCH + q * 16) = v;
    }
    if (!FIRST) {
        for (int j = tid; j < 1440; j += 512) {       // h: 180 px * 8 chunks
            const int p = j >> 3, q = j & 7;
            const int gy = y0 + p / 10 - 1, gx = x0 + p % 10 - 1;
            uint4 v = make_uint4(0u, 0u, 0u, 0u);
            if ((unsigned)gy < H_ && (unsigned)gx < W_)
                v = *(const uint4*)(hframe + ((size_t)gy * W_ + gx) * F_ + q * 8);
            *(uint4*)(sm + SM_HH + p * HH_PITCH + q * 16) = v;
        }
    }
    __syncthreads();   // the only barrier before the epilogue

    // ---- per-lane A ldmatrix base addresses ----
    const uint32_t sb = smem_u32(sm);
    const int hi  = (lane >> 4) << 4;
    const int m0  = warp_m * 32 + (lane & 15);
    const int m1  = m0 + 16;
    const int f0p = (m0 >> 3) * 10 + (m0 & 7);
    const int f1p = (m1 >> 3) * 10 + (m1 & 7);
    const uint32_t aAx0 = sb + SM_XH + f0p * XH_PITCH + hi;
    const uint32_t aAx1 = sb + SM_XH + f1p * XH_PITCH + hi;
    const uint32_t aAh0 = sb + SM_HH + f0p * HH_PITCH + hi;
    const uint32_t aAh1 = sb + SM_HH + f1p * HH_PITCH + hi;

    float d[2][8][4];
    #pragma unroll
    for (int mt = 0; mt < 2; ++mt)
        #pragma unroll
        for (int nt = 0; nt < 8; ++nt)
            #pragma unroll
            for (int c = 0; c < 4; ++c) d[mt][nt][c] = 0.f;

    const int NS = FIRST ? 9 : NSL;
    // B fragment pointers (uint4 units; group idx stride = 32 uint4 = 512B)
    const uint4* bp = &g_bf[0][warp_n][0][lane];
    uint4 bb[4];
    bb[0] = bp[0];
    bb[1] = bp[32];

    #define SLICE_BODY(A0, A1, SOFF)                                          \
    do {                                                                      \
        const uint4* bnp = bp + ((s + 1 < NS) ? (4 * 8 * 32) : 0);            \
        _Pragma("unroll")                                                     \
        for (int kk = 0; kk < 2; ++kk) {                                      \
            uint32_t a0r[4], a1r[4];                                          \
            LDSM4(a0r[0], a0r[1], a0r[2], a0r[3], (A0) + (SOFF) + kk * 32);   \
            LDSM4(a1r[0], a1r[1], a1r[2], a1r[3], (A1) + (SOFF) + kk * 32);   \
            _Pragma("unroll")                                                 \
            for (int p = 0; p < 4; ++p) {                                     \
                const int idx = kk * 4 + p;                                   \
                const uint4* pf = (idx + 2 < 8) ? (bp + (idx + 2) * 32)       \
                                                : (bnp + (idx - 6) * 32);     \
                uint4 nb = *pf;                                               \
                uint4 cb = bb[p];                                             \
                MMA16816(d[0][2 * p + 0], a0r[0], a0r[1], a0r[2], a0r[3], cb.x, cb.y); \
                MMA16816(d[0][2 * p + 1], a0r[0], a0r[1], a0r[2], a0r[3], cb.z, cb.w); \
                MMA16816(d[1][2 * p + 0], a1r[0], a1r[1], a1r[2], a1r[3], cb.x, cb.y); \
                MMA16816(d[1][2 * p + 1], a1r[0], a1r[1], a1r[2], a1r[3], cb.z, cb.w); \
                bb[(p + 2) & 3] = nb;                                         \
            }                                                                 \
        }                                                                     \
        bp = bnp;                                                             \
    } while (0)

    // x-conv slices
    for (int s = 0; s < 9; ++s) {
        const int ky = s / 3, kx = s - 3 * (s / 3);
        const uint32_t soff = (uint32_t)(ky * 10 + kx) * XH_PITCH;
        SLICE_BODY(aAx0, aAx1, soff);
    }
    // h-conv slices
    if (!FIRST) {
        for (int s = 9; s < NSL; ++s) {
            const int u = s - 9, k9 = u >> 1, c0 = (u & 1) * 32;
            const int ky = k9 / 3, kx = k9 - 3 * (k9 / 3);
            const uint32_t soff = (uint32_t)(ky * 10 + kx) * HH_PITCH + c0 * 2;
            SLICE_BODY(aAh0, aAh1, soff);
        }
    }
    #undef SLICE_BODY

    // ================= fused LSTM epilogue (verified layout) ==============
    __half* hhout = g_hh[hsel ^ 1];
    const int fq = 2 * (lane & 3);

    #pragma unroll
    for (int mt = 0; mt < 2; ++mt) {
        #pragma unroll
        for (int rh = 0; rh < 2; ++rh) {
            const int m  = warp_m * 32 + mt * 16 + rh * 8 + (lane >> 2);
            const int py = m >> 3, px = m & 7;
            const size_t pix =
                (((size_t)b * H_ + (y0 + py)) * W_ + (x0 + px)) * F_;
            #pragma unroll
            for (int t1 = 0; t1 < 2; ++t1) {
                const int f0 = warp_n * 16 + t1 * 8 + fq;
                float zi0 = d[mt][0 + t1][rh * 2 + 0], zi1 = d[mt][0 + t1][rh * 2 + 1];
                float zf0 = d[mt][2 + t1][rh * 2 + 0], zf1 = d[mt][2 + t1][rh * 2 + 1];
                float zc0 = d[mt][4 + t1][rh * 2 + 0], zc1 = d[mt][4 + t1][rh * 2 + 1];
                float zo0 = d[mt][6 + t1][rh * 2 + 0], zo1 = d[mt][6 + t1][rh * 2 + 1];

                float2 co = make_float2(0.f, 0.f);
                if (!FIRST) co = *(const float2*)&g_c[pix + f0];

                float ig0 = hsig(zi0 + bias[f0]);
                float fg0 = hsig(zf0 + bias[64 + f0]);
                float zz0 =      zc0 + bias[128 + f0];
                float og0 = hsig(zo0 + bias[192 + f0]);
                float cn0 = fg0 * co.x + ig0 * fmaxf(zz0, 0.f);
                float hn0 = og0 * fmaxf(cn0, 0.f);

                float ig1 = hsig(zi1 + bias[f0 + 1]);
                float fg1 = hsig(zf1 + bias[65 + f0]);
                float zz1 =      zc1 + bias[129 + f0];
                float og1 = hsig(zo1 + bias[193 + f0]);
                float cn1 = fg1 * co.y + ig1 * fmaxf(zz1, 0.f);
                float hn1 = og1 * fmaxf(cn1, 0.f);

                if (!last) {
                    *(float2*)&g_c[pix + f0] = make_float2(cn0, cn1);
                    *(__half2*)&hhout[pix + f0] = __floats2half2_rn(hn0, hn1);
                } else {
                    *(float2*)&out[pix + f0] = make_float2(hn0, hn1);
                }
            }
        }
    }
}

extern "C" void kernel_launch(void* const* d_in, const int* in_sizes, int n_in,
                              void* d_out, int out_size)
{
    const float* x = nullptr; const float* Wt = nullptr;
    const float* Ut = nullptr; const float* bias = nullptr;
    for (int i = 0; i < n_in; ++i) {
        switch (in_sizes[i]) {
            case B_*T_*H_*W_*CIN: x    = (const float*)d_in[i]; break;
            case 3*3*CIN*NC:      Wt   = (const float*)d_in[i]; break;
            case 3*3*F_*NC:       Ut   = (const float*)d_in[i]; break;
            case NC:              bias = (const float*)d_in[i]; break;
        }
    }
    if (!x || !Wt || !Ut || !bias) {
        x = (const float*)d_in[0]; Wt = (const float*)d_in[1];
        Ut = (const float*)d_in[2]; bias = (const float*)d_in[3];
    }
    float* out = (float*)d_out;

    prep_x<<<(B_ * T_ * H_ * W_ * CIN) / 1024, 256>>>(x);
    prep_bf<<<dim3(NSL, 4), 256>>>(Wt, Ut);

    dim3 grid(W_ / 8, H_ / 16, B_);   // (8, 4, 8) = 256 CTAs, M=128 each
    dim3 block(512);

    step_mma<true><<<grid, block>>>(bias, 0, 0, out, 0);
    for (int t = 1; t < T_; ++t) {
        int last = (t == T_ - 1);
        step_mma<false><<<grid, block>>>(bias, t, t & 1, out, last);
    }
}